// round 1
// baseline (speedup 1.0000x reference)
#include <cuda_runtime.h>
#include <cstdint>

#define N_NODES 100000
#define N_EDGES 1600000
#define D 128

// Scratch (device globals: allocation-free per harness rules)
__device__ float g_agg[(size_t)N_NODES * D];
__device__ float g_h0[(size_t)N_NODES * D];
__device__ float g_h1[(size_t)N_NODES * D];

// ---------------------------------------------------------------------------
// Zero the aggregation buffer
// ---------------------------------------------------------------------------
__global__ void zero_agg_kernel() {
    float4* p = reinterpret_cast<float4*>(g_agg);
    const int n4 = (N_NODES * D) / 4;
    int i = blockIdx.x * blockDim.x + threadIdx.x;
    int stride = gridDim.x * blockDim.x;
    float4 z = make_float4(0.f, 0.f, 0.f, 0.f);
    for (; i < n4; i += stride) p[i] = z;
}

// ---------------------------------------------------------------------------
// Edge aggregation: g_agg[dst] += w * h[src]   (one warp per edge, float4/lane)
// ---------------------------------------------------------------------------
__device__ __forceinline__ void red_add_v4(float* p, float a, float b, float c, float d) {
    asm volatile("red.global.add.v4.f32 [%0], {%1, %2, %3, %4};"
                 :: "l"(p), "f"(a), "f"(b), "f"(c), "f"(d) : "memory");
}

__global__ __launch_bounds__(256) void edge_kernel(
    const float* __restrict__ h,
    const float* __restrict__ ew,
    const int* __restrict__ src,
    const int* __restrict__ dst) {
    int w = (blockIdx.x * 256 + threadIdx.x) >> 5;
    if (w >= N_EDGES) return;
    int lane = threadIdx.x & 31;
    int s = src[w];
    int d = dst[w];
    float wt = ew[w];
    float4 v = *(reinterpret_cast<const float4*>(h + (size_t)s * D) + lane);
    red_add_v4(g_agg + (size_t)d * D + lane * 4, v.x * wt, v.y * wt, v.z * wt, v.w * wt);
}

// ---------------------------------------------------------------------------
// Fused dense: out = maybe_relu( g_agg @ Wrel^T + hin @ Wroot^T + b )
// Treated as one [N x 256] @ [256 x 128] GEMM (K split: first 128 from agg/Wrel,
// second 128 from hin/Wroot). Tile: 64 rows x 128 cols, BK=16, 256 threads,
// each thread 8x4 register tile.
// ---------------------------------------------------------------------------
__global__ __launch_bounds__(256) void gemm_kernel(
    const float* __restrict__ hin,
    const float* __restrict__ Wrel,
    const float* __restrict__ Wroot,
    const float* __restrict__ bias,
    float* __restrict__ out,
    int do_relu) {
    __shared__ float Xs[16][64];
    __shared__ float Ws[16][128];

    const int row0 = blockIdx.x * 64;
    const int tid = threadIdx.x;
    const int cg = tid & 31;   // column group: cols cg*4 .. cg*4+3
    const int rg = tid >> 5;   // row group:    rows rg*8 .. rg*8+7

    float acc[8][4];
#pragma unroll
    for (int r = 0; r < 8; ++r)
#pragma unroll
        for (int c = 0; c < 4; ++c) acc[r][c] = 0.f;

    // X-tile load indices (1024 floats: 256 threads x float4)
    const int xi = tid * 4;
    const int xr = xi >> 4;   // 0..63
    const int xk = xi & 15;   // {0,4,8,12}

    for (int t = 0; t < 16; ++t) {
        const float* Xsrc = (t < 8) ? g_agg : hin;
        const float* Wsrc = (t < 8) ? Wrel : Wroot;
        const int k0 = (t & 7) * 16;

        // Global loads
        float4 xv = make_float4(0.f, 0.f, 0.f, 0.f);
        const int grow = row0 + xr;
        if (grow < N_NODES)
            xv = *reinterpret_cast<const float4*>(Xsrc + (size_t)grow * D + k0 + xk);

        float4 wv[2];
#pragma unroll
        for (int p = 0; p < 2; ++p) {
            const int i = xi + p * 1024;
            const int wc = i >> 4;
            const int wk = i & 15;
            wv[p] = *reinterpret_cast<const float4*>(Wsrc + (size_t)wc * D + k0 + wk);
        }

        // Shared stores (transposed: [k][row/col])
        Xs[xk + 0][xr] = xv.x;
        Xs[xk + 1][xr] = xv.y;
        Xs[xk + 2][xr] = xv.z;
        Xs[xk + 3][xr] = xv.w;
#pragma unroll
        for (int p = 0; p < 2; ++p) {
            const int i = xi + p * 1024;
            const int wc = i >> 4;
            const int wk = i & 15;
            Ws[wk + 0][wc] = wv[p].x;
            Ws[wk + 1][wc] = wv[p].y;
            Ws[wk + 2][wc] = wv[p].z;
            Ws[wk + 3][wc] = wv[p].w;
        }
        __syncthreads();

#pragma unroll
        for (int kk = 0; kk < 16; ++kk) {
            float4 x0 = *reinterpret_cast<const float4*>(&Xs[kk][rg * 8]);
            float4 x1 = *reinterpret_cast<const float4*>(&Xs[kk][rg * 8 + 4]);
            float4 w4 = *reinterpret_cast<const float4*>(&Ws[kk][cg * 4]);
            float xr8[8] = {x0.x, x0.y, x0.z, x0.w, x1.x, x1.y, x1.z, x1.w};
            float wc4[4] = {w4.x, w4.y, w4.z, w4.w};
#pragma unroll
            for (int r = 0; r < 8; ++r)
#pragma unroll
                for (int c = 0; c < 4; ++c)
                    acc[r][c] = fmaf(xr8[r], wc4[c], acc[r][c]);
        }
        __syncthreads();
    }

    // Epilogue: bias + optional relu, float4 stores
    const int c0 = cg * 4;
    const float4 bv = *reinterpret_cast<const float4*>(bias + c0);
#pragma unroll
    for (int r = 0; r < 8; ++r) {
        const int grow = row0 + rg * 8 + r;
        if (grow < N_NODES) {
            float4 o;
            o.x = acc[r][0] + bv.x;
            o.y = acc[r][1] + bv.y;
            o.z = acc[r][2] + bv.z;
            o.w = acc[r][3] + bv.w;
            if (do_relu) {
                o.x = fmaxf(o.x, 0.f);
                o.y = fmaxf(o.y, 0.f);
                o.z = fmaxf(o.z, 0.f);
                o.w = fmaxf(o.w, 0.f);
            }
            *reinterpret_cast<float4*>(out + (size_t)grow * D + c0) = o;
        }
    }
}

// ---------------------------------------------------------------------------
// Launch: 3 layers of { zero agg; edge scatter; fused GEMM+bias(+relu) }
// ---------------------------------------------------------------------------
extern "C" void kernel_launch(void* const* d_in, const int* in_sizes, int n_in,
                              void* d_out, int out_size) {
    const float* x   = (const float*)d_in[0];
    const float* ew  = (const float*)d_in[1];
    const float* Wr0 = (const float*)d_in[2];
    const float* Wo0 = (const float*)d_in[3];
    const float* b0  = (const float*)d_in[4];
    const float* Wr1 = (const float*)d_in[5];
    const float* Wo1 = (const float*)d_in[6];
    const float* b1  = (const float*)d_in[7];
    const float* Wr2 = (const float*)d_in[8];
    const float* Wo2 = (const float*)d_in[9];
    const float* b2  = (const float*)d_in[10];
    const int* src   = (const int*)d_in[11];
    const int* dst   = (const int*)d_in[12];
    float* out = (float*)d_out;

    float *h0p = nullptr, *h1p = nullptr;
    cudaGetSymbolAddress((void**)&h0p, g_h0);
    cudaGetSymbolAddress((void**)&h1p, g_h1);

    const int edge_blocks = (N_EDGES * 32 + 255) / 256;   // 1 warp per edge
    const int gemm_blocks = (N_NODES + 63) / 64;

    // Layer 0
    zero_agg_kernel<<<2048, 256>>>();
    edge_kernel<<<edge_blocks, 256>>>(x, ew, src, dst);
    gemm_kernel<<<gemm_blocks, 256>>>(x, Wr0, Wo0, b0, h0p, 1);

    // Layer 1
    zero_agg_kernel<<<2048, 256>>>();
    edge_kernel<<<edge_blocks, 256>>>(h0p, ew, src, dst);
    gemm_kernel<<<gemm_blocks, 256>>>(h0p, Wr1, Wo1, b1, h1p, 1);

    // Layer 2
    zero_agg_kernel<<<2048, 256>>>();
    edge_kernel<<<edge_blocks, 256>>>(h1p, ew, src, dst);
    gemm_kernel<<<gemm_blocks, 256>>>(h1p, Wr2, Wo2, b2, out, 0);
}

// round 3
// speedup vs baseline: 1.3157x; 1.3157x over previous
#include <cuda_runtime.h>
#include <cuda_bf16.h>
#include <cstdint>

#define N_NODES 100000
#define N_EDGES 1600000
#define D 128

// Scratch (device globals: allocation-free per harness rules)
__device__ float g_agg[(size_t)N_NODES * D];
__device__ float g_h0[(size_t)N_NODES * D];
__device__ float g_h1[(size_t)N_NODES * D];

// ===========================================================================
// Zero agg buffer
// ===========================================================================
__global__ void zero_agg_kernel() {
    float4* p = reinterpret_cast<float4*>(g_agg);
    const int n4 = (N_NODES * D) / 4;
    int i = blockIdx.x * blockDim.x + threadIdx.x;
    int stride = gridDim.x * blockDim.x;
    float4 z = make_float4(0.f, 0.f, 0.f, 0.f);
    for (; i < n4; i += stride) p[i] = z;
}

// ===========================================================================
// Edge aggregation: g_agg[dst] += w * h[src]  (one warp/edge, red.v4)
// ===========================================================================
__device__ __forceinline__ void red_add_v4(float* p, float a, float b, float c, float d) {
    asm volatile("red.global.add.v4.f32 [%0], {%1, %2, %3, %4};"
                 :: "l"(p), "f"(a), "f"(b), "f"(c), "f"(d) : "memory");
}

__global__ __launch_bounds__(256) void edge_kernel(
    const float* __restrict__ h,
    const float* __restrict__ ew,
    const int* __restrict__ src,
    const int* __restrict__ dst) {
    int w = (blockIdx.x * 256 + threadIdx.x) >> 5;
    if (w >= N_EDGES) return;
    int lane = threadIdx.x & 31;
    int s = src[w];
    int d = dst[w];
    float wt = ew[w];
    float4 v = *(reinterpret_cast<const float4*>(h + (size_t)s * D) + lane);
    red_add_v4(g_agg + (size_t)d * D + lane * 4, v.x * wt, v.y * wt, v.z * wt, v.w * wt);
}

// ===========================================================================
// bf16-split tensor-core GEMM via mma.sync (HMMA.16816):
//   out = maybe_relu( agg @ Wrel^T + hin @ Wroot^T + b )
// CTA: 128(M) x 128(N), K=256 in 8 chunks of 32. 8 warps, each 64x32.
// Each fp32 -> bf16 hi + bf16 lo;  acc += Ahi*Bhi + Ahi*Blo + Alo*Bhi.
// ===========================================================================
#define PITCH_H 40          // smem row pitch in halves (80 bytes, conflict-free)
#define MAT_BYTES (128 * PITCH_H * 2)   // 10240
#define STAGE_BYTES (4 * MAT_BYTES)     // 40960
#define OFF_BIAS 0
#define OFF_ST 512
#define GSMEM_BYTES (OFF_ST + 2 * STAGE_BYTES)  // 82432
#define M_AHI 0
#define M_ALO MAT_BYTES
#define M_WHI (2 * MAT_BYTES)
#define M_WLO (3 * MAT_BYTES)

__device__ __forceinline__ void mma_bf16(float* c, const uint32_t* a, const uint32_t* b) {
    asm volatile(
        "mma.sync.aligned.m16n8k16.row.col.f32.bf16.bf16.f32 "
        "{%0,%1,%2,%3}, {%4,%5,%6,%7}, {%8,%9}, {%0,%1,%2,%3};"
        : "+f"(c[0]), "+f"(c[1]), "+f"(c[2]), "+f"(c[3])
        : "r"(a[0]), "r"(a[1]), "r"(a[2]), "r"(a[3]), "r"(b[0]), "r"(b[1]));
}

__device__ __forceinline__ uint32_t pack_hi(float x, float y) {
    __nv_bfloat162 p = __floats2bfloat162_rn(x, y);
    return *reinterpret_cast<uint32_t*>(&p);
}

// split float4 -> (hi packed as 2x u32, lo packed as 2x u32)
__device__ __forceinline__ void split_pack(float4 v, uint2& hi, uint2& lo) {
    __nv_bfloat16 hx = __float2bfloat16(v.x);
    __nv_bfloat16 hy = __float2bfloat16(v.y);
    __nv_bfloat16 hz = __float2bfloat16(v.z);
    __nv_bfloat16 hw = __float2bfloat16(v.w);
    float lx = v.x - __bfloat162float(hx);
    float ly = v.y - __bfloat162float(hy);
    float lz = v.z - __bfloat162float(hz);
    float lw = v.w - __bfloat162float(hw);
    __nv_bfloat162 h01; h01.x = hx; h01.y = hy;
    __nv_bfloat162 h23; h23.x = hz; h23.y = hw;
    hi.x = *reinterpret_cast<uint32_t*>(&h01);
    hi.y = *reinterpret_cast<uint32_t*>(&h23);
    lo.x = pack_hi(lx, ly);
    lo.y = pack_hi(lz, lw);
}

__global__ __launch_bounds__(256, 1) void gemm_mma_kernel(
    const float* __restrict__ hin,
    const float* __restrict__ Wrel,
    const float* __restrict__ Wroot,
    const float* __restrict__ bias,
    float* __restrict__ out,
    int do_relu) {
    extern __shared__ char smem[];
    const int tid = threadIdx.x;
    const int wid = tid >> 5;
    const int lid = tid & 31;
    const int row0 = blockIdx.x * 128;
    const int wm = wid >> 2;      // 0..1  -> M offset wm*64
    const int wn = wid & 3;       // 0..3  -> N offset wn*32

    if (tid < 128) ((float*)(smem + OFF_BIAS))[tid] = bias[tid];

    // accumulators: 4 mtiles x 4 ntiles x 4 f32
    float acc[4][4][4];
#pragma unroll
    for (int i = 0; i < 4; ++i)
#pragma unroll
        for (int j = 0; j < 4; ++j)
#pragma unroll
            for (int r = 0; r < 4; ++r) acc[i][j][r] = 0.f;

    // global-load indices: 4 float4 each for A and W per chunk
    const int lrow = tid >> 3;    // 0..31 (advance by 32 per p)
    const int kq = tid & 7;       // float4 slot within 32-wide chunk

    float4 aPre[4], wPre[4];

    // prefetch chunk 0
    {
        const float* Xs = g_agg;
        const float* Ws = Wrel;
#pragma unroll
        for (int p = 0; p < 4; ++p) {
            const int r = p * 32 + lrow;
            const int gr = row0 + r;
            aPre[p] = (gr < N_NODES)
                ? *reinterpret_cast<const float4*>(Xs + (size_t)gr * D + kq * 4)
                : make_float4(0.f, 0.f, 0.f, 0.f);
            wPre[p] = *reinterpret_cast<const float4*>(Ws + (size_t)r * D + kq * 4);
        }
    }

    for (int t = 0; t < 8; ++t) {
        const int s = t & 1;
        char* st = smem + OFF_ST + s * STAGE_BYTES;

        // store prefetched chunk into smem stage s (split hi/lo)
#pragma unroll
        for (int p = 0; p < 4; ++p) {
            const int r = p * 32 + lrow;
            const uint32_t boff = (uint32_t)r * (PITCH_H * 2) + kq * 8;
            uint2 hi, lo;
            split_pack(aPre[p], hi, lo);
            *reinterpret_cast<uint2*>(st + M_AHI + boff) = hi;
            *reinterpret_cast<uint2*>(st + M_ALO + boff) = lo;
            split_pack(wPre[p], hi, lo);
            *reinterpret_cast<uint2*>(st + M_WHI + boff) = hi;
            *reinterpret_cast<uint2*>(st + M_WLO + boff) = lo;
        }
        __syncthreads();

        // prefetch next chunk (overlaps compute below)
        if (t < 7) {
            const int tn = t + 1;
            const float* Xs = (tn < 4) ? g_agg : hin;
            const float* Ws = (tn < 4) ? Wrel : Wroot;
            const int k0 = (tn & 3) * 32;
#pragma unroll
            for (int p = 0; p < 4; ++p) {
                const int r = p * 32 + lrow;
                const int gr = row0 + r;
                aPre[p] = (gr < N_NODES)
                    ? *reinterpret_cast<const float4*>(Xs + (size_t)gr * D + k0 + kq * 4)
                    : make_float4(0.f, 0.f, 0.f, 0.f);
                wPre[p] = *reinterpret_cast<const float4*>(Ws + (size_t)r * D + k0 + kq * 4);
            }
        }

        // compute on stage s: 2 k16 steps
        const uint32_t* Ah = reinterpret_cast<const uint32_t*>(st + M_AHI);
        const uint32_t* Al = reinterpret_cast<const uint32_t*>(st + M_ALO);
        const uint32_t* Wh = reinterpret_cast<const uint32_t*>(st + M_WHI);
        const uint32_t* Wl = reinterpret_cast<const uint32_t*>(st + M_WLO);
        const int lr = lid >> 2;       // 0..7
        const int lc = (lid & 3) * 2;  // 0,2,4,6

#pragma unroll
        for (int ks = 0; ks < 2; ++ks) {
            const int kb = ks * 16;
            // A fragments (hi & lo) for 4 mtiles
            uint32_t afh[4][4], afl[4][4];
#pragma unroll
            for (int i = 0; i < 4; ++i) {
                const int rbase = wm * 64 + i * 16 + lr;
                const uint32_t i00 = (uint32_t)rbase * (PITCH_H / 2) + ((kb + lc) >> 1);
                const uint32_t i10 = i00 + 8 * (PITCH_H / 2);
                afh[i][0] = Ah[i00];     afh[i][1] = Ah[i10];
                afh[i][2] = Ah[i00 + 4]; afh[i][3] = Ah[i10 + 4];
                afl[i][0] = Al[i00];     afl[i][1] = Al[i10];
                afl[i][2] = Al[i00 + 4]; afl[i][3] = Al[i10 + 4];
            }
            // B fragments (hi & lo) for 4 ntiles
            uint32_t bfh[4][2], bfl[4][2];
#pragma unroll
            for (int j = 0; j < 4; ++j) {
                const int nbase = wn * 32 + j * 8 + lr;
                const uint32_t i0 = (uint32_t)nbase * (PITCH_H / 2) + ((kb + lc) >> 1);
                bfh[j][0] = Wh[i0]; bfh[j][1] = Wh[i0 + 4];
                bfl[j][0] = Wl[i0]; bfl[j][1] = Wl[i0 + 4];
            }
#pragma unroll
            for (int i = 0; i < 4; ++i)
#pragma unroll
                for (int j = 0; j < 4; ++j) {
                    mma_bf16(acc[i][j], afh[i], bfh[j]);
                    mma_bf16(acc[i][j], afh[i], bfl[j]);
                    mma_bf16(acc[i][j], afl[i], bfh[j]);
                }
        }
        __syncthreads();
    }

    // Epilogue: bias + optional relu, float2 stores
    const float* sB = (const float*)(smem + OFF_BIAS);
    const int lr = lid >> 2;
    const int lc = (lid & 3) * 2;
#pragma unroll
    for (int i = 0; i < 4; ++i) {
        const int r_lo = row0 + wm * 64 + i * 16 + lr;
        const int r_hi = r_lo + 8;
#pragma unroll
        for (int j = 0; j < 4; ++j) {
            const int col = wn * 32 + j * 8 + lc;
            const float bx = sB[col], by = sB[col + 1];
            if (r_lo < N_NODES) {
                float2 o;
                o.x = acc[i][j][0] + bx;
                o.y = acc[i][j][1] + by;
                if (do_relu) { o.x = fmaxf(o.x, 0.f); o.y = fmaxf(o.y, 0.f); }
                *reinterpret_cast<float2*>(out + (size_t)r_lo * D + col) = o;
            }
            if (r_hi < N_NODES) {
                float2 o;
                o.x = acc[i][j][2] + bx;
                o.y = acc[i][j][3] + by;
                if (do_relu) { o.x = fmaxf(o.x, 0.f); o.y = fmaxf(o.y, 0.f); }
                *reinterpret_cast<float2*>(out + (size_t)r_hi * D + col) = o;
            }
        }
    }
}

// ===========================================================================
// Launch: 3 layers of { zero agg; edge scatter; mma GEMM+bias(+relu) }
// ===========================================================================
extern "C" void kernel_launch(void* const* d_in, const int* in_sizes, int n_in,
                              void* d_out, int out_size) {
    const float* x   = (const float*)d_in[0];
    const float* ew  = (const float*)d_in[1];
    const float* Wr0 = (const float*)d_in[2];
    const float* Wo0 = (const float*)d_in[3];
    const float* b0  = (const float*)d_in[4];
    const float* Wr1 = (const float*)d_in[5];
    const float* Wo1 = (const float*)d_in[6];
    const float* b1  = (const float*)d_in[7];
    const float* Wr2 = (const float*)d_in[8];
    const float* Wo2 = (const float*)d_in[9];
    const float* b2  = (const float*)d_in[10];
    const int* src   = (const int*)d_in[11];
    const int* dst   = (const int*)d_in[12];
    float* out = (float*)d_out;

    float *h0p = nullptr, *h1p = nullptr;
    cudaGetSymbolAddress((void**)&h0p, g_h0);
    cudaGetSymbolAddress((void**)&h1p, g_h1);

    cudaFuncSetAttribute(gemm_mma_kernel, cudaFuncAttributeMaxDynamicSharedMemorySize, GSMEM_BYTES);

    const int edge_blocks = (N_EDGES * 32 + 255) / 256;   // 1 warp per edge
    const int gemm_blocks = (N_NODES + 127) / 128;        // 782

    // Layer 0
    zero_agg_kernel<<<2048, 256>>>();
    edge_kernel<<<edge_blocks, 256>>>(x, ew, src, dst);
    gemm_mma_kernel<<<gemm_blocks, 256, GSMEM_BYTES>>>(x, Wr0, Wo0, b0, h0p, 1);

    // Layer 1
    zero_agg_kernel<<<2048, 256>>>();
    edge_kernel<<<edge_blocks, 256>>>(h0p, ew, src, dst);
    gemm_mma_kernel<<<gemm_blocks, 256, GSMEM_BYTES>>>(h0p, Wr1, Wo1, b1, h1p, 1);

    // Layer 2
    zero_agg_kernel<<<2048, 256>>>();
    edge_kernel<<<edge_blocks, 256>>>(h1p, ew, src, dst);
    gemm_mma_kernel<<<gemm_blocks, 256, GSMEM_BYTES>>>(h1p, Wr2, Wo2, b2, out, 0);
}

// round 4
// speedup vs baseline: 2.3693x; 1.8008x over previous
#include <cuda_runtime.h>
#include <cuda_bf16.h>
#include <cstdint>

#define N_NODES 100000
#define N_EDGES 1600000
#define D 128
#define NB_SCAN 391          // ceil(N_NODES/256)

// Scratch (device globals: allocation-free per harness rules)
__device__ float g_agg[(size_t)N_NODES * D];
__device__ float g_h0[(size_t)N_NODES * D];
__device__ float g_h1[(size_t)N_NODES * D];
__device__ int   g_deg[N_NODES];
__device__ int   g_off[N_NODES + 1];
__device__ int   g_cursor[N_NODES];
__device__ int   g_bsum[512];
__device__ int2  g_csr[N_EDGES];     // (src, weight-as-int)

// ===========================================================================
// CSR build: zero deg -> histogram -> block sums -> scan -> offsets -> scatter
// ===========================================================================
__global__ void zero_deg_kernel() {
    int i = blockIdx.x * blockDim.x + threadIdx.x;
    if (i < N_NODES) g_deg[i] = 0;
}

__global__ __launch_bounds__(256) void hist_kernel(const int* __restrict__ dst) {
    int e = blockIdx.x * blockDim.x + threadIdx.x;
    if (e < N_EDGES) atomicAdd(&g_deg[dst[e]], 1);
}

__global__ __launch_bounds__(256) void blocksum_kernel() {
    __shared__ int s[256];
    int i = blockIdx.x * 256 + threadIdx.x;
    s[threadIdx.x] = (i < N_NODES) ? g_deg[i] : 0;
    __syncthreads();
    for (int d = 128; d > 0; d >>= 1) {
        if (threadIdx.x < d) s[threadIdx.x] += s[threadIdx.x + d];
        __syncthreads();
    }
    if (threadIdx.x == 0) g_bsum[blockIdx.x] = s[0];
}

__global__ __launch_bounds__(512) void scan_bsum_kernel() {
    __shared__ int s[512];
    int t = threadIdx.x;
    s[t] = (t < NB_SCAN) ? g_bsum[t] : 0;
    __syncthreads();
    for (int d = 1; d < 512; d <<= 1) {
        int v = (t >= d) ? s[t - d] : 0;
        __syncthreads();
        s[t] += v;
        __syncthreads();
    }
    if (t < NB_SCAN) g_bsum[t] = (t == 0) ? 0 : s[t - 1];   // exclusive
}

__global__ __launch_bounds__(256) void offsets_kernel() {
    __shared__ int s[256];
    int t = threadIdx.x;
    int i = blockIdx.x * 256 + t;
    int v = (i < N_NODES) ? g_deg[i] : 0;
    s[t] = v;
    __syncthreads();
    for (int d = 1; d < 256; d <<= 1) {
        int u = (t >= d) ? s[t - d] : 0;
        __syncthreads();
        s[t] += u;
        __syncthreads();
    }
    int excl = s[t] - v + g_bsum[blockIdx.x];
    if (i < N_NODES) {
        g_off[i] = excl;
        g_cursor[i] = excl;
        if (i == N_NODES - 1) g_off[N_NODES] = excl + v;
    }
}

__global__ __launch_bounds__(256) void scatter_kernel(
    const int* __restrict__ src, const int* __restrict__ dst,
    const float* __restrict__ ew) {
    int e = blockIdx.x * blockDim.x + threadIdx.x;
    if (e >= N_EDGES) return;
    int d = dst[e];
    int p = atomicAdd(&g_cursor[d], 1);
    g_csr[p] = make_int2(src[e], __float_as_int(ew[e]));
}

// ===========================================================================
// CSR aggregation: one warp per node, register acc, single coalesced write
// ===========================================================================
__global__ __launch_bounds__(256) void agg_kernel(const float* __restrict__ h) {
    int warp = (blockIdx.x * 256 + threadIdx.x) >> 5;
    if (warp >= N_NODES) return;
    const int lane = threadIdx.x & 31;
    const int beg = g_off[warp];
    const int end = g_off[warp + 1];

    float4 acc = make_float4(0.f, 0.f, 0.f, 0.f);
    int e = beg;
    for (; e + 2 <= end; e += 2) {
        int2 p0 = g_csr[e];
        int2 p1 = g_csr[e + 1];
        const float4 v0 = *(reinterpret_cast<const float4*>(h + (size_t)p0.x * D) + lane);
        const float4 v1 = *(reinterpret_cast<const float4*>(h + (size_t)p1.x * D) + lane);
        const float w0 = __int_as_float(p0.y);
        const float w1 = __int_as_float(p1.y);
        acc.x = fmaf(w0, v0.x, acc.x); acc.y = fmaf(w0, v0.y, acc.y);
        acc.z = fmaf(w0, v0.z, acc.z); acc.w = fmaf(w0, v0.w, acc.w);
        acc.x = fmaf(w1, v1.x, acc.x); acc.y = fmaf(w1, v1.y, acc.y);
        acc.z = fmaf(w1, v1.z, acc.z); acc.w = fmaf(w1, v1.w, acc.w);
    }
    if (e < end) {
        int2 p0 = g_csr[e];
        const float4 v0 = *(reinterpret_cast<const float4*>(h + (size_t)p0.x * D) + lane);
        const float w0 = __int_as_float(p0.y);
        acc.x = fmaf(w0, v0.x, acc.x); acc.y = fmaf(w0, v0.y, acc.y);
        acc.z = fmaf(w0, v0.z, acc.z); acc.w = fmaf(w0, v0.w, acc.w);
    }
    *(reinterpret_cast<float4*>(g_agg + (size_t)warp * D) + lane) = acc;
}

// ===========================================================================
// bf16-split tensor-core GEMM via mma.sync (HMMA.16816):
//   out = maybe_relu( agg @ Wrel^T + hin @ Wroot^T + b )
// CTA: 128(M) x 128(N), K=256 in 8 chunks of 32. 8 warps, each 64x32.
// fp32 -> bf16 hi + bf16 lo;  acc += Ahi*Bhi + Ahi*Blo + Alo*Bhi.
// ===========================================================================
#define PITCH_H 40
#define MAT_BYTES (128 * PITCH_H * 2)
#define STAGE_BYTES (4 * MAT_BYTES)
#define OFF_BIAS 0
#define OFF_ST 512
#define GSMEM_BYTES (OFF_ST + 2 * STAGE_BYTES)
#define M_AHI 0
#define M_ALO MAT_BYTES
#define M_WHI (2 * MAT_BYTES)
#define M_WLO (3 * MAT_BYTES)

__device__ __forceinline__ void mma_bf16(float* c, const uint32_t* a, const uint32_t* b) {
    asm volatile(
        "mma.sync.aligned.m16n8k16.row.col.f32.bf16.bf16.f32 "
        "{%0,%1,%2,%3}, {%4,%5,%6,%7}, {%8,%9}, {%0,%1,%2,%3};"
        : "+f"(c[0]), "+f"(c[1]), "+f"(c[2]), "+f"(c[3])
        : "r"(a[0]), "r"(a[1]), "r"(a[2]), "r"(a[3]), "r"(b[0]), "r"(b[1]));
}

__device__ __forceinline__ uint32_t pack_hi(float x, float y) {
    __nv_bfloat162 p = __floats2bfloat162_rn(x, y);
    return *reinterpret_cast<uint32_t*>(&p);
}

__device__ __forceinline__ void split_pack(float4 v, uint2& hi, uint2& lo) {
    __nv_bfloat16 hx = __float2bfloat16(v.x);
    __nv_bfloat16 hy = __float2bfloat16(v.y);
    __nv_bfloat16 hz = __float2bfloat16(v.z);
    __nv_bfloat16 hw = __float2bfloat16(v.w);
    float lx = v.x - __bfloat162float(hx);
    float ly = v.y - __bfloat162float(hy);
    float lz = v.z - __bfloat162float(hz);
    float lw = v.w - __bfloat162float(hw);
    __nv_bfloat162 h01; h01.x = hx; h01.y = hy;
    __nv_bfloat162 h23; h23.x = hz; h23.y = hw;
    hi.x = *reinterpret_cast<uint32_t*>(&h01);
    hi.y = *reinterpret_cast<uint32_t*>(&h23);
    lo.x = pack_hi(lx, ly);
    lo.y = pack_hi(lz, lw);
}

__global__ __launch_bounds__(256, 1) void gemm_mma_kernel(
    const float* __restrict__ hin,
    const float* __restrict__ Wrel,
    const float* __restrict__ Wroot,
    const float* __restrict__ bias,
    float* __restrict__ out,
    int do_relu) {
    extern __shared__ char smem[];
    const int tid = threadIdx.x;
    const int wid = tid >> 5;
    const int lid = tid & 31;
    const int row0 = blockIdx.x * 128;
    const int wm = wid >> 2;
    const int wn = wid & 3;

    if (tid < 128) ((float*)(smem + OFF_BIAS))[tid] = bias[tid];

    float acc[4][4][4];
#pragma unroll
    for (int i = 0; i < 4; ++i)
#pragma unroll
        for (int j = 0; j < 4; ++j)
#pragma unroll
            for (int r = 0; r < 4; ++r) acc[i][j][r] = 0.f;

    const int lrow = tid >> 3;
    const int kq = tid & 7;

    float4 aPre[4], wPre[4];
    {
        const float* Xs = g_agg;
        const float* Ws = Wrel;
#pragma unroll
        for (int p = 0; p < 4; ++p) {
            const int r = p * 32 + lrow;
            const int gr = row0 + r;
            aPre[p] = (gr < N_NODES)
                ? *reinterpret_cast<const float4*>(Xs + (size_t)gr * D + kq * 4)
                : make_float4(0.f, 0.f, 0.f, 0.f);
            wPre[p] = *reinterpret_cast<const float4*>(Ws + (size_t)r * D + kq * 4);
        }
    }

    for (int t = 0; t < 8; ++t) {
        const int s = t & 1;
        char* st = smem + OFF_ST + s * STAGE_BYTES;

#pragma unroll
        for (int p = 0; p < 4; ++p) {
            const int r = p * 32 + lrow;
            const uint32_t boff = (uint32_t)r * (PITCH_H * 2) + kq * 8;
            uint2 hi, lo;
            split_pack(aPre[p], hi, lo);
            *reinterpret_cast<uint2*>(st + M_AHI + boff) = hi;
            *reinterpret_cast<uint2*>(st + M_ALO + boff) = lo;
            split_pack(wPre[p], hi, lo);
            *reinterpret_cast<uint2*>(st + M_WHI + boff) = hi;
            *reinterpret_cast<uint2*>(st + M_WLO + boff) = lo;
        }
        __syncthreads();

        if (t < 7) {
            const int tn = t + 1;
            const float* Xs = (tn < 4) ? g_agg : hin;
            const float* Ws = (tn < 4) ? Wrel : Wroot;
            const int k0 = (tn & 3) * 32;
#pragma unroll
            for (int p = 0; p < 4; ++p) {
                const int r = p * 32 + lrow;
                const int gr = row0 + r;
                aPre[p] = (gr < N_NODES)
                    ? *reinterpret_cast<const float4*>(Xs + (size_t)gr * D + k0 + kq * 4)
                    : make_float4(0.f, 0.f, 0.f, 0.f);
                wPre[p] = *reinterpret_cast<const float4*>(Ws + (size_t)r * D + k0 + kq * 4);
            }
        }

        const uint32_t* Ah = reinterpret_cast<const uint32_t*>(st + M_AHI);
        const uint32_t* Al = reinterpret_cast<const uint32_t*>(st + M_ALO);
        const uint32_t* Wh = reinterpret_cast<const uint32_t*>(st + M_WHI);
        const uint32_t* Wl = reinterpret_cast<const uint32_t*>(st + M_WLO);
        const int lr = lid >> 2;
        const int lc = (lid & 3) * 2;

#pragma unroll
        for (int ks = 0; ks < 2; ++ks) {
            const int kb = ks * 16;
            uint32_t afh[4][4], afl[4][4];
#pragma unroll
            for (int i = 0; i < 4; ++i) {
                const int rbase = wm * 64 + i * 16 + lr;
                const uint32_t i00 = (uint32_t)rbase * (PITCH_H / 2) + ((kb + lc) >> 1);
                const uint32_t i10 = i00 + 8 * (PITCH_H / 2);
                afh[i][0] = Ah[i00];     afh[i][1] = Ah[i10];
                afh[i][2] = Ah[i00 + 4]; afh[i][3] = Ah[i10 + 4];
                afl[i][0] = Al[i00];     afl[i][1] = Al[i10];
                afl[i][2] = Al[i00 + 4]; afl[i][3] = Al[i10 + 4];
            }
            uint32_t bfh[4][2], bfl[4][2];
#pragma unroll
            for (int j = 0; j < 4; ++j) {
                const int nbase = wn * 32 + j * 8 + lr;
                const uint32_t i0 = (uint32_t)nbase * (PITCH_H / 2) + ((kb + lc) >> 1);
                bfh[j][0] = Wh[i0]; bfh[j][1] = Wh[i0 + 4];
                bfl[j][0] = Wl[i0]; bfl[j][1] = Wl[i0 + 4];
            }
#pragma unroll
            for (int i = 0; i < 4; ++i)
#pragma unroll
                for (int j = 0; j < 4; ++j) {
                    mma_bf16(acc[i][j], afh[i], bfh[j]);
                    mma_bf16(acc[i][j], afh[i], bfl[j]);
                    mma_bf16(acc[i][j], afl[i], bfh[j]);
                }
        }
        __syncthreads();
    }

    const float* sB = (const float*)(smem + OFF_BIAS);
    const int lr = lid >> 2;
    const int lc = (lid & 3) * 2;
#pragma unroll
    for (int i = 0; i < 4; ++i) {
        const int r_lo = row0 + wm * 64 + i * 16 + lr;
        const int r_hi = r_lo + 8;
#pragma unroll
        for (int j = 0; j < 4; ++j) {
            const int col = wn * 32 + j * 8 + lc;
            const float bx = sB[col], by = sB[col + 1];
            if (r_lo < N_NODES) {
                float2 o;
                o.x = acc[i][j][0] + bx;
                o.y = acc[i][j][1] + by;
                if (do_relu) { o.x = fmaxf(o.x, 0.f); o.y = fmaxf(o.y, 0.f); }
                *reinterpret_cast<float2*>(out + (size_t)r_lo * D + col) = o;
            }
            if (r_hi < N_NODES) {
                float2 o;
                o.x = acc[i][j][2] + bx;
                o.y = acc[i][j][3] + by;
                if (do_relu) { o.x = fmaxf(o.x, 0.f); o.y = fmaxf(o.y, 0.f); }
                *reinterpret_cast<float2*>(out + (size_t)r_hi * D + col) = o;
            }
        }
    }
}

// ===========================================================================
// Launch: CSR build once; then 3 layers of { csr-agg; mma GEMM+bias(+relu) }
// ===========================================================================
extern "C" void kernel_launch(void* const* d_in, const int* in_sizes, int n_in,
                              void* d_out, int out_size) {
    const float* x   = (const float*)d_in[0];
    const float* ew  = (const float*)d_in[1];
    const float* Wr0 = (const float*)d_in[2];
    const float* Wo0 = (const float*)d_in[3];
    const float* b0  = (const float*)d_in[4];
    const float* Wr1 = (const float*)d_in[5];
    const float* Wo1 = (const float*)d_in[6];
    const float* b1  = (const float*)d_in[7];
    const float* Wr2 = (const float*)d_in[8];
    const float* Wo2 = (const float*)d_in[9];
    const float* b2  = (const float*)d_in[10];
    const int* src   = (const int*)d_in[11];
    const int* dst   = (const int*)d_in[12];
    float* out = (float*)d_out;

    float *h0p = nullptr, *h1p = nullptr;
    cudaGetSymbolAddress((void**)&h0p, g_h0);
    cudaGetSymbolAddress((void**)&h1p, g_h1);

    cudaFuncSetAttribute(gemm_mma_kernel, cudaFuncAttributeMaxDynamicSharedMemorySize, GSMEM_BYTES);

    const int edge_blocks = (N_EDGES + 255) / 256;     // 6250
    const int agg_blocks  = (N_NODES * 32 + 255) / 256; // 12500 (warp/node)
    const int gemm_blocks = (N_NODES + 127) / 128;     // 782

    // --- CSR build (once per call; reused by all 3 layers) ---
    zero_deg_kernel<<<NB_SCAN, 256>>>();
    hist_kernel<<<edge_blocks, 256>>>(dst);
    blocksum_kernel<<<NB_SCAN, 256>>>();
    scan_bsum_kernel<<<1, 512>>>();
    offsets_kernel<<<NB_SCAN, 256>>>();
    scatter_kernel<<<edge_blocks, 256>>>(src, dst, ew);

    // Layer 0
    agg_kernel<<<agg_blocks, 256>>>(x);
    gemm_mma_kernel<<<gemm_blocks, 256, GSMEM_BYTES>>>(x, Wr0, Wo0, b0, h0p, 1);

    // Layer 1
    agg_kernel<<<agg_blocks, 256>>>(h0p);
    gemm_mma_kernel<<<gemm_blocks, 256, GSMEM_BYTES>>>(h0p, Wr1, Wo1, b1, h1p, 1);

    // Layer 2
    agg_kernel<<<agg_blocks, 256>>>(h1p);
    gemm_mma_kernel<<<gemm_blocks, 256, GSMEM_BYTES>>>(h1p, Wr2, Wo2, b2, out, 0);
}

// round 5
// speedup vs baseline: 2.7433x; 1.1579x over previous
#include <cuda_runtime.h>
#include <cuda_fp16.h>
#include <cstdint>

#define N_NODES 100000
#define N_EDGES 1600000
#define D 128
#define NB_SCAN 391          // ceil(N_NODES/256)

// Scratch (device globals: allocation-free per harness rules)
__device__ float  g_h0[(size_t)N_NODES * D];
__device__ float  g_h1[(size_t)N_NODES * D];
__device__ __half g_aggP[(size_t)N_NODES * D];   // agg, fp16-rounded
__device__ __half g_P0[(size_t)N_NODES * D];     // x plane / h1 plane
__device__ __half g_P1[(size_t)N_NODES * D];     // h0 plane
__device__ __half g_WH[3 * 128 * 256];           // [layer][n][k256] hi
__device__ __half g_WL[3 * 128 * 256];           // lo
__device__ int    g_deg[N_NODES];
__device__ int    g_off[N_NODES + 1];
__device__ int    g_cursor[N_NODES];
__device__ int    g_bsum[512];
__device__ int2   g_csr[N_EDGES];                // (src, weight-as-int)

// ===========================================================================
// small PTX helpers
// ===========================================================================
__device__ __forceinline__ uint32_t smem_u32(const void* p) {
    uint32_t a;
    asm("{ .reg .u64 t; cvta.to.shared.u64 t, %1; cvt.u32.u64 %0, t; }" : "=r"(a) : "l"(p));
    return a;
}
__device__ __forceinline__ void ldsm_x4(uint32_t* r, uint32_t addr) {
    asm volatile("ldmatrix.sync.aligned.m8n8.x4.shared.b16 {%0,%1,%2,%3}, [%4];"
                 : "=r"(r[0]), "=r"(r[1]), "=r"(r[2]), "=r"(r[3]) : "r"(addr));
}
__device__ __forceinline__ void ldsm_x2(uint32_t* r, uint32_t addr) {
    asm volatile("ldmatrix.sync.aligned.m8n8.x2.shared.b16 {%0,%1}, [%2];"
                 : "=r"(r[0]), "=r"(r[1]) : "r"(addr));
}
__device__ __forceinline__ void cp16(uint32_t dst, const void* src) {
    asm volatile("cp.async.cg.shared.global [%0], [%1], 16;" :: "r"(dst), "l"(src));
}
__device__ __forceinline__ void mma_f16(float* c, const uint32_t* a, const uint32_t* b) {
    asm volatile(
        "mma.sync.aligned.m16n8k16.row.col.f32.f16.f16.f32 "
        "{%0,%1,%2,%3}, {%4,%5,%6,%7}, {%8,%9}, {%0,%1,%2,%3};"
        : "+f"(c[0]), "+f"(c[1]), "+f"(c[2]), "+f"(c[3])
        : "r"(a[0]), "r"(a[1]), "r"(a[2]), "r"(a[3]), "r"(b[0]), "r"(b[1]));
}

// ===========================================================================
// CSR build: zero deg -> histogram -> block sums -> scan -> offsets -> scatter
// ===========================================================================
__global__ void zero_deg_kernel() {
    int i = blockIdx.x * blockDim.x + threadIdx.x;
    if (i < N_NODES) g_deg[i] = 0;
}

__global__ __launch_bounds__(256) void hist_kernel(const int* __restrict__ dst) {
    int e = blockIdx.x * blockDim.x + threadIdx.x;
    if (e < N_EDGES) atomicAdd(&g_deg[dst[e]], 1);
}

__global__ __launch_bounds__(256) void blocksum_kernel() {
    __shared__ int s[256];
    int i = blockIdx.x * 256 + threadIdx.x;
    s[threadIdx.x] = (i < N_NODES) ? g_deg[i] : 0;
    __syncthreads();
    for (int d = 128; d > 0; d >>= 1) {
        if (threadIdx.x < d) s[threadIdx.x] += s[threadIdx.x + d];
        __syncthreads();
    }
    if (threadIdx.x == 0) g_bsum[blockIdx.x] = s[0];
}

__global__ __launch_bounds__(512) void scan_bsum_kernel() {
    __shared__ int s[512];
    int t = threadIdx.x;
    s[t] = (t < NB_SCAN) ? g_bsum[t] : 0;
    __syncthreads();
    for (int d = 1; d < 512; d <<= 1) {
        int v = (t >= d) ? s[t - d] : 0;
        __syncthreads();
        s[t] += v;
        __syncthreads();
    }
    if (t < NB_SCAN) g_bsum[t] = (t == 0) ? 0 : s[t - 1];   // exclusive
}

__global__ __launch_bounds__(256) void offsets_kernel() {
    __shared__ int s[256];
    int t = threadIdx.x;
    int i = blockIdx.x * 256 + t;
    int v = (i < N_NODES) ? g_deg[i] : 0;
    s[t] = v;
    __syncthreads();
    for (int d = 1; d < 256; d <<= 1) {
        int u = (t >= d) ? s[t - d] : 0;
        __syncthreads();
        s[t] += u;
        __syncthreads();
    }
    int excl = s[t] - v + g_bsum[blockIdx.x];
    if (i < N_NODES) {
        g_off[i] = excl;
        g_cursor[i] = excl;
        if (i == N_NODES - 1) g_off[N_NODES] = excl + v;
    }
}

__global__ __launch_bounds__(256) void scatter_kernel(
    const int* __restrict__ src, const int* __restrict__ dst,
    const float* __restrict__ ew) {
    int e = blockIdx.x * blockDim.x + threadIdx.x;
    if (e >= N_EDGES) return;
    int d = dst[e];
    int p = atomicAdd(&g_cursor[d], 1);
    g_csr[p] = make_int2(src[e], __float_as_int(ew[e]));
}

// ===========================================================================
// Pre-split weights: g_WH/g_WL[l][n][k256], k<128 from Wrel, k>=128 from Wroot
// ===========================================================================
__global__ __launch_bounds__(256) void presplit_w_kernel(
    const float* __restrict__ Wr0, const float* __restrict__ Wo0,
    const float* __restrict__ Wr1, const float* __restrict__ Wo1,
    const float* __restrict__ Wr2, const float* __restrict__ Wo2) {
    int idx = blockIdx.x * 256 + threadIdx.x;
    if (idx >= 3 * 128 * 256) return;
    int l = idx >> 15;
    int rem = idx & 32767;
    int n = rem >> 8;
    int k = rem & 255;
    const float* Wr = (l == 0) ? Wr0 : (l == 1) ? Wr1 : Wr2;
    const float* Wo = (l == 0) ? Wo0 : (l == 1) ? Wo1 : Wo2;
    float w = (k < 128) ? Wr[n * 128 + k] : Wo[n * 128 + (k - 128)];
    __half hi = __float2half_rn(w);
    float lo = w - __half2float(hi);
    g_WH[idx] = hi;
    g_WL[idx] = __float2half_rn(lo);
}

// x -> fp16 plane (P0)
__global__ __launch_bounds__(256) void split_x_kernel(const float* __restrict__ x) {
    int i = blockIdx.x * 256 + threadIdx.x;
    if (i >= N_NODES * D / 2) return;
    float2 v = reinterpret_cast<const float2*>(x)[i];
    __half2 h = __floats2half2_rn(v.x, v.y);
    reinterpret_cast<__half2*>(g_P0)[i] = h;
}

// ===========================================================================
// CSR aggregation: one warp per node; fp32 acc; writes fp16 plane g_aggP
// ===========================================================================
__global__ __launch_bounds__(256) void agg_kernel(const float* __restrict__ h) {
    int warp = (blockIdx.x * 256 + threadIdx.x) >> 5;
    if (warp >= N_NODES) return;
    const int lane = threadIdx.x & 31;
    const int beg = g_off[warp];
    const int end = g_off[warp + 1];

    float4 acc = make_float4(0.f, 0.f, 0.f, 0.f);
    int e = beg;
    for (; e + 2 <= end; e += 2) {
        int2 p0 = g_csr[e];
        int2 p1 = g_csr[e + 1];
        const float4 v0 = *(reinterpret_cast<const float4*>(h + (size_t)p0.x * D) + lane);
        const float4 v1 = *(reinterpret_cast<const float4*>(h + (size_t)p1.x * D) + lane);
        const float w0 = __int_as_float(p0.y);
        const float w1 = __int_as_float(p1.y);
        acc.x = fmaf(w0, v0.x, acc.x); acc.y = fmaf(w0, v0.y, acc.y);
        acc.z = fmaf(w0, v0.z, acc.z); acc.w = fmaf(w0, v0.w, acc.w);
        acc.x = fmaf(w1, v1.x, acc.x); acc.y = fmaf(w1, v1.y, acc.y);
        acc.z = fmaf(w1, v1.z, acc.z); acc.w = fmaf(w1, v1.w, acc.w);
    }
    if (e < end) {
        int2 p0 = g_csr[e];
        const float4 v0 = *(reinterpret_cast<const float4*>(h + (size_t)p0.x * D) + lane);
        const float w0 = __int_as_float(p0.y);
        acc.x = fmaf(w0, v0.x, acc.x); acc.y = fmaf(w0, v0.y, acc.y);
        acc.z = fmaf(w0, v0.z, acc.z); acc.w = fmaf(w0, v0.w, acc.w);
    }
    __half2 a = __floats2half2_rn(acc.x, acc.y);
    __half2 b = __floats2half2_rn(acc.z, acc.w);
    uint2 st;
    st.x = *reinterpret_cast<uint32_t*>(&a);
    st.y = *reinterpret_cast<uint32_t*>(&b);
    *reinterpret_cast<uint2*>(reinterpret_cast<char*>(g_aggP) + (size_t)warp * 256 + lane * 8) = st;
}

// ===========================================================================
// GEMM v3: out = maybe_relu( Ahi @ (Whi+Wlo)^T + b ), A = [aggP | hinP] K=256
// CTA 128x128, 8 chunks of K=32. 3-stage cp.async pipeline, ldmatrix frags.
// Also writes fp16 plane of the output (for next layer's GEMM) when outP!=0.
// ===========================================================================
#define STAGE_BYTES 24576
#define PL_A 0
#define PL_WH 8192
#define PL_WL 16384
#define OFF_STG 1024
#define GSMEM (OFF_STG + 3 * STAGE_BYTES)   // 74752

// swizzled byte offset within an 8KB plane: row pitch 64B, 16B slot XOR
__device__ __forceinline__ uint32_t swz(int row, int grp) {
    return (uint32_t)row * 64 + (uint32_t)((grp ^ ((row >> 1) & 3)) << 4);
}

__device__ __forceinline__ void fill_stage(
    uint32_t stg, const __half* __restrict__ aP, int k0A,
    const __half* __restrict__ wh, const __half* __restrict__ wl, int k0W,
    int row0, int tid) {
#pragma unroll
    for (int q = 0; q < 2; ++q) {
        const int i = tid * 2 + q;      // 0..511
        const int row = i >> 2;         // 0..127
        const int grp = i & 3;          // 16B group
        const uint32_t d = swz(row, grp);
        const int gr = row0 + row;
        if (gr < N_NODES) {
            cp16(stg + PL_A + d, aP + (size_t)gr * D + k0A + grp * 8);
        } else {
            asm volatile("st.shared.v4.b32 [%0], {%1,%1,%1,%1};"
                         :: "r"(stg + PL_A + d), "r"(0));
        }
        cp16(stg + PL_WH + d, wh + row * 256 + k0W + grp * 8);
        cp16(stg + PL_WL + d, wl + row * 256 + k0W + grp * 8);
    }
}

__global__ __launch_bounds__(256) void gemm_v3_kernel(
    const __half* __restrict__ hinP,
    const __half* __restrict__ WH,    // [128][256] this layer
    const __half* __restrict__ WL,
    const float* __restrict__ bias,
    float* __restrict__ out,
    __half* __restrict__ outP,        // may be null
    int do_relu) {
    extern __shared__ char smem[];
    const uint32_t sb = smem_u32(smem);
    const int tid = threadIdx.x;
    const int wid = tid >> 5;
    const int lane = tid & 31;
    const int row0 = blockIdx.x * 128;
    const int wm = wid >> 2;   // M offset wm*64
    const int wn = wid & 3;    // N offset wn*32

    if (tid < 128) ((float*)smem)[tid] = bias[tid];

    float acc[4][4][4];
#pragma unroll
    for (int i = 0; i < 4; ++i)
#pragma unroll
        for (int j = 0; j < 4; ++j)
#pragma unroll
            for (int r = 0; r < 4; ++r) acc[i][j][r] = 0.f;

    // prologue: fill stages 0..2 (chunks 0..2)
#pragma unroll
    for (int t = 0; t < 3; ++t) {
        const __half* aP = (t < 4) ? g_aggP : hinP;
        fill_stage(sb + OFF_STG + t * STAGE_BYTES, aP, (t & 3) * 32,
                   WH, WL, t * 32, row0, tid);
        asm volatile("cp.async.commit_group;" ::: "memory");
    }

    for (int t = 0; t < 8; ++t) {
        asm volatile("cp.async.wait_group 2;" ::: "memory");
        __syncthreads();

        // compute on stage t%3
        const uint32_t stg = sb + OFF_STG + (t % 3) * STAGE_BYTES;
#pragma unroll
        for (int ks = 0; ks < 2; ++ks) {
            const int kb = ks * 16;
            uint32_t af[4][4];
#pragma unroll
            for (int i = 0; i < 4; ++i) {
                const int m0 = wm * 64 + i * 16;
                const int r = m0 + (lane & 7) + ((lane & 8) ? 8 : 0);
                const int g = (kb >> 3) + (lane >> 4);
                ldsm_x4(af[i], stg + PL_A + swz(r, g));
            }
            uint32_t bh[4][2], bl[4][2];
#pragma unroll
            for (int j = 0; j < 4; ++j) {
                const int n0 = wn * 32 + j * 8;
                const int l15 = lane & 15;
                const int r = n0 + (l15 & 7);
                const int g = (kb >> 3) + (l15 >> 3);
                ldsm_x2(bh[j], stg + PL_WH + swz(r, g));
                ldsm_x2(bl[j], stg + PL_WL + swz(r, g));
            }
#pragma unroll
            for (int i = 0; i < 4; ++i)
#pragma unroll
                for (int j = 0; j < 4; ++j) {
                    mma_f16(acc[i][j], af[i], bh[j]);
                    mma_f16(acc[i][j], af[i], bl[j]);
                }
        }
        __syncthreads();

        const int tn = t + 3;
        if (tn < 8) {
            const __half* aP = (tn < 4) ? g_aggP : hinP;
            fill_stage(sb + OFF_STG + (tn % 3) * STAGE_BYTES, aP, (tn & 3) * 32,
                       WH, WL, tn * 32, row0, tid);
        }
        asm volatile("cp.async.commit_group;" ::: "memory");
    }

    // epilogue: bias (+relu), fp32 store, optional fp16 plane store
    const float* sB = (const float*)smem;
    const int lr = lane >> 2;
    const int lc = (lane & 3) * 2;
#pragma unroll
    for (int i = 0; i < 4; ++i) {
        const int r_lo = row0 + wm * 64 + i * 16 + lr;
        const int r_hi = r_lo + 8;
#pragma unroll
        for (int j = 0; j < 4; ++j) {
            const int col = wn * 32 + j * 8 + lc;
            const float bx = sB[col], by = sB[col + 1];
            if (r_lo < N_NODES) {
                float2 o;
                o.x = acc[i][j][0] + bx;
                o.y = acc[i][j][1] + by;
                if (do_relu) { o.x = fmaxf(o.x, 0.f); o.y = fmaxf(o.y, 0.f); }
                *reinterpret_cast<float2*>(out + (size_t)r_lo * D + col) = o;
                if (outP) {
                    __half2 hp = __floats2half2_rn(o.x, o.y);
                    *reinterpret_cast<uint32_t*>(
                        reinterpret_cast<char*>(outP) + ((size_t)r_lo * D + col) * 2) =
                        *reinterpret_cast<uint32_t*>(&hp);
                }
            }
            if (r_hi < N_NODES) {
                float2 o;
                o.x = acc[i][j][2] + bx;
                o.y = acc[i][j][3] + by;
                if (do_relu) { o.x = fmaxf(o.x, 0.f); o.y = fmaxf(o.y, 0.f); }
                *reinterpret_cast<float2*>(out + (size_t)r_hi * D + col) = o;
                if (outP) {
                    __half2 hp = __floats2half2_rn(o.x, o.y);
                    *reinterpret_cast<uint32_t*>(
                        reinterpret_cast<char*>(outP) + ((size_t)r_hi * D + col) * 2) =
                        *reinterpret_cast<uint32_t*>(&hp);
                }
            }
        }
    }
}

// ===========================================================================
// Launch
// ===========================================================================
extern "C" void kernel_launch(void* const* d_in, const int* in_sizes, int n_in,
                              void* d_out, int out_size) {
    const float* x   = (const float*)d_in[0];
    const float* ew  = (const float*)d_in[1];
    const float* Wr0 = (const float*)d_in[2];
    const float* Wo0 = (const float*)d_in[3];
    const float* b0  = (const float*)d_in[4];
    const float* Wr1 = (const float*)d_in[5];
    const float* Wo1 = (const float*)d_in[6];
    const float* b1  = (const float*)d_in[7];
    const float* Wr2 = (const float*)d_in[8];
    const float* Wo2 = (const float*)d_in[9];
    const float* b2  = (const float*)d_in[10];
    const int* src   = (const int*)d_in[11];
    const int* dst   = (const int*)d_in[12];
    float* out = (float*)d_out;

    float *h0p = nullptr, *h1p = nullptr;
    __half *p0 = nullptr, *p1 = nullptr, *whB = nullptr, *wlB = nullptr;
    cudaGetSymbolAddress((void**)&h0p, g_h0);
    cudaGetSymbolAddress((void**)&h1p, g_h1);
    cudaGetSymbolAddress((void**)&p0, g_P0);
    cudaGetSymbolAddress((void**)&p1, g_P1);
    cudaGetSymbolAddress((void**)&whB, g_WH);
    cudaGetSymbolAddress((void**)&wlB, g_WL);

    cudaFuncSetAttribute(gemm_v3_kernel, cudaFuncAttributeMaxDynamicSharedMemorySize, GSMEM);

    const int edge_blocks = (N_EDGES + 255) / 256;
    const int agg_blocks  = (N_NODES * 32 + 255) / 256;
    const int gemm_blocks = (N_NODES + 127) / 128;

    // one-time preprocessing
    zero_deg_kernel<<<NB_SCAN, 256>>>();
    hist_kernel<<<edge_blocks, 256>>>(dst);
    presplit_w_kernel<<<384, 256>>>(Wr0, Wo0, Wr1, Wo1, Wr2, Wo2);
    split_x_kernel<<<25000, 256>>>(x);
    blocksum_kernel<<<NB_SCAN, 256>>>();
    scan_bsum_kernel<<<1, 512>>>();
    offsets_kernel<<<NB_SCAN, 256>>>();
    scatter_kernel<<<edge_blocks, 256>>>(src, dst, ew);

    // Layer 0: A = [agg(x) | x]
    agg_kernel<<<agg_blocks, 256>>>(x);
    gemm_v3_kernel<<<gemm_blocks, 256, GSMEM>>>(p0, whB, wlB, b0, h0p, p1, 1);

    // Layer 1: A = [agg(h0) | h0]
    agg_kernel<<<agg_blocks, 256>>>(h0p);
    gemm_v3_kernel<<<gemm_blocks, 256, GSMEM>>>(p1, whB + 32768, wlB + 32768, b1, h1p, p0, 1);

    // Layer 2: A = [agg(h1) | h1], final output fp32 only
    agg_kernel<<<agg_blocks, 256>>>(h1p);
    gemm_v3_kernel<<<gemm_blocks, 256, GSMEM>>>(p0, whB + 65536, wlB + 65536, b2, out, nullptr, 0);
}

// round 6
// speedup vs baseline: 3.3033x; 1.2041x over previous
#include <cuda_runtime.h>
#include <cuda_fp16.h>
#include <cstdint>

#define N_NODES 100000
#define N_EDGES 1600000
#define D 128
#define NB_SCAN 391          // ceil(N_NODES/256)

// Scratch (device globals: allocation-free per harness rules)
__device__ __half g_aggP[(size_t)N_NODES * D];   // agg, fp16
__device__ __half g_P0[(size_t)N_NODES * D];     // x / h1 plane
__device__ __half g_P1[(size_t)N_NODES * D];     // h0 plane
__device__ __half g_WH[3 * 128 * 256];           // [layer][n][k256] hi
__device__ __half g_WL[3 * 128 * 256];           // lo
__device__ int    g_deg[N_NODES];
__device__ int    g_off[N_NODES + 1];
__device__ int    g_cursor[N_NODES];
__device__ int    g_bsum[512];
__device__ int2   g_csr[N_EDGES];                // (src, weight-as-int)

// ===========================================================================
// small PTX helpers
// ===========================================================================
__device__ __forceinline__ uint32_t smem_u32(const void* p) {
    uint32_t a;
    asm("{ .reg .u64 t; cvta.to.shared.u64 t, %1; cvt.u32.u64 %0, t; }" : "=r"(a) : "l"(p));
    return a;
}
__device__ __forceinline__ void ldsm_x4(uint32_t* r, uint32_t addr) {
    asm volatile("ldmatrix.sync.aligned.m8n8.x4.shared.b16 {%0,%1,%2,%3}, [%4];"
                 : "=r"(r[0]), "=r"(r[1]), "=r"(r[2]), "=r"(r[3]) : "r"(addr));
}
__device__ __forceinline__ void ldsm_x2(uint32_t* r, uint32_t addr) {
    asm volatile("ldmatrix.sync.aligned.m8n8.x2.shared.b16 {%0,%1}, [%2];"
                 : "=r"(r[0]), "=r"(r[1]) : "r"(addr));
}
__device__ __forceinline__ void cp16(uint32_t dst, const void* src) {
    asm volatile("cp.async.cg.shared.global [%0], [%1], 16;" :: "r"(dst), "l"(src));
}
__device__ __forceinline__ void mma_f16(float* c, const uint32_t* a, const uint32_t* b) {
    asm volatile(
        "mma.sync.aligned.m16n8k16.row.col.f32.f16.f16.f32 "
        "{%0,%1,%2,%3}, {%4,%5,%6,%7}, {%8,%9}, {%0,%1,%2,%3};"
        : "+f"(c[0]), "+f"(c[1]), "+f"(c[2]), "+f"(c[3])
        : "r"(a[0]), "r"(a[1]), "r"(a[2]), "r"(a[3]), "r"(b[0]), "r"(b[1]));
}

// ===========================================================================
// CSR build: zero deg -> histogram -> block sums -> scan -> offsets -> scatter
// ===========================================================================
__global__ void zero_deg_kernel() {
    int i = blockIdx.x * blockDim.x + threadIdx.x;
    if (i < N_NODES) g_deg[i] = 0;
}

__global__ __launch_bounds__(256) void hist_kernel(const int* __restrict__ dst) {
    int e = blockIdx.x * blockDim.x + threadIdx.x;
    if (e < N_EDGES) atomicAdd(&g_deg[dst[e]], 1);
}

__global__ __launch_bounds__(256) void blocksum_kernel() {
    __shared__ int s[256];
    int i = blockIdx.x * 256 + threadIdx.x;
    s[threadIdx.x] = (i < N_NODES) ? g_deg[i] : 0;
    __syncthreads();
    for (int d = 128; d > 0; d >>= 1) {
        if (threadIdx.x < d) s[threadIdx.x] += s[threadIdx.x + d];
        __syncthreads();
    }
    if (threadIdx.x == 0) g_bsum[blockIdx.x] = s[0];
}

__global__ __launch_bounds__(512) void scan_bsum_kernel() {
    __shared__ int s[512];
    int t = threadIdx.x;
    s[t] = (t < NB_SCAN) ? g_bsum[t] : 0;
    __syncthreads();
    for (int d = 1; d < 512; d <<= 1) {
        int v = (t >= d) ? s[t - d] : 0;
        __syncthreads();
        s[t] += v;
        __syncthreads();
    }
    if (t < NB_SCAN) g_bsum[t] = (t == 0) ? 0 : s[t - 1];   // exclusive
}

__global__ __launch_bounds__(256) void offsets_kernel() {
    __shared__ int s[256];
    int t = threadIdx.x;
    int i = blockIdx.x * 256 + t;
    int v = (i < N_NODES) ? g_deg[i] : 0;
    s[t] = v;
    __syncthreads();
    for (int d = 1; d < 256; d <<= 1) {
        int u = (t >= d) ? s[t - d] : 0;
        __syncthreads();
        s[t] += u;
        __syncthreads();
    }
    int excl = s[t] - v + g_bsum[blockIdx.x];
    if (i < N_NODES) {
        g_off[i] = excl;
        g_cursor[i] = excl;
        if (i == N_NODES - 1) g_off[N_NODES] = excl + v;
    }
}

__global__ __launch_bounds__(256) void scatter_kernel(
    const int* __restrict__ src, const int* __restrict__ dst,
    const float* __restrict__ ew) {
    int e = blockIdx.x * blockDim.x + threadIdx.x;
    if (e >= N_EDGES) return;
    int d = dst[e];
    int p = atomicAdd(&g_cursor[d], 1);
    g_csr[p] = make_int2(src[e], __float_as_int(ew[e]));
}

// ===========================================================================
// Pre-split weights: g_WH/g_WL[l][n][k256], k<128 from Wrel, k>=128 from Wroot
// ===========================================================================
__global__ __launch_bounds__(256) void presplit_w_kernel(
    const float* __restrict__ Wr0, const float* __restrict__ Wo0,
    const float* __restrict__ Wr1, const float* __restrict__ Wo1,
    const float* __restrict__ Wr2, const float* __restrict__ Wo2) {
    int idx = blockIdx.x * 256 + threadIdx.x;
    if (idx >= 3 * 128 * 256) return;
    int l = idx >> 15;
    int rem = idx & 32767;
    int n = rem >> 8;
    int k = rem & 255;
    const float* Wr = (l == 0) ? Wr0 : (l == 1) ? Wr1 : Wr2;
    const float* Wo = (l == 0) ? Wo0 : (l == 1) ? Wo1 : Wo2;
    float w = (k < 128) ? Wr[n * 128 + k] : Wo[n * 128 + (k - 128)];
    __half hi = __float2half_rn(w);
    float lo = w - __half2float(hi);
    g_WH[idx] = hi;
    g_WL[idx] = __float2half_rn(lo);
}

// x -> fp16 plane (P0)
__global__ __launch_bounds__(256) void split_x_kernel(const float* __restrict__ x) {
    int i = blockIdx.x * 256 + threadIdx.x;
    if (i >= N_NODES * D / 2) return;
    float2 v = reinterpret_cast<const float2*>(x)[i];
    __half2 h = __floats2half2_rn(v.x, v.y);
    reinterpret_cast<__half2*>(g_P0)[i] = h;
}

// ===========================================================================
// CSR aggregation from fp16 plane: one warp/node, lane owns 4 channels.
// fp32 accumulate, fp16 plane output. 256 B gather per edge.
// ===========================================================================
__global__ __launch_bounds__(256) void agg_kernel(const __half* __restrict__ hP) {
    int node = (blockIdx.x * 256 + threadIdx.x) >> 5;
    if (node >= N_NODES) return;
    const int lane = threadIdx.x & 31;
    const int beg = g_off[node];
    const int end = g_off[node + 1];
    const char* base = reinterpret_cast<const char*>(hP) + lane * 8;

    float4 acc = make_float4(0.f, 0.f, 0.f, 0.f);
    int e = beg;
    for (; e + 2 <= end; e += 2) {
        const int2 p0 = g_csr[e];
        const int2 p1 = g_csr[e + 1];
        const uint2 r0 = *reinterpret_cast<const uint2*>(base + (size_t)p0.x * 256);
        const uint2 r1 = *reinterpret_cast<const uint2*>(base + (size_t)p1.x * 256);
        const float w0 = __int_as_float(p0.y);
        const float w1 = __int_as_float(p1.y);
        float2 a0 = __half22float2(*reinterpret_cast<const __half2*>(&r0.x));
        float2 b0 = __half22float2(*reinterpret_cast<const __half2*>(&r0.y));
        float2 a1 = __half22float2(*reinterpret_cast<const __half2*>(&r1.x));
        float2 b1 = __half22float2(*reinterpret_cast<const __half2*>(&r1.y));
        acc.x = fmaf(w0, a0.x, acc.x); acc.y = fmaf(w0, a0.y, acc.y);
        acc.z = fmaf(w0, b0.x, acc.z); acc.w = fmaf(w0, b0.y, acc.w);
        acc.x = fmaf(w1, a1.x, acc.x); acc.y = fmaf(w1, a1.y, acc.y);
        acc.z = fmaf(w1, b1.x, acc.z); acc.w = fmaf(w1, b1.y, acc.w);
    }
    if (e < end) {
        const int2 p0 = g_csr[e];
        const uint2 r0 = *reinterpret_cast<const uint2*>(base + (size_t)p0.x * 256);
        const float w0 = __int_as_float(p0.y);
        float2 a0 = __half22float2(*reinterpret_cast<const __half2*>(&r0.x));
        float2 b0 = __half22float2(*reinterpret_cast<const __half2*>(&r0.y));
        acc.x = fmaf(w0, a0.x, acc.x); acc.y = fmaf(w0, a0.y, acc.y);
        acc.z = fmaf(w0, b0.x, acc.z); acc.w = fmaf(w0, b0.y, acc.w);
    }
    __half2 a = __floats2half2_rn(acc.x, acc.y);
    __half2 b = __floats2half2_rn(acc.z, acc.w);
    uint2 st;
    st.x = *reinterpret_cast<uint32_t*>(&a);
    st.y = *reinterpret_cast<uint32_t*>(&b);
    *reinterpret_cast<uint2*>(reinterpret_cast<char*>(g_aggP) + (size_t)node * 256 + lane * 8) = st;
}

// ===========================================================================
// GEMM: out = maybe_relu( A @ (Whi+Wlo)^T + b ), A = [aggP | hinP], K=256
// CTA 128x128, 8 chunks of K=32. 3-stage cp.async pipeline, ldmatrix frags.
// fp32 store only when out != null (last layer); fp16 plane when outP != null.
// ===========================================================================
#define STAGE_BYTES 24576
#define PL_A 0
#define PL_WH 8192
#define PL_WL 16384
#define OFF_STG 1024
#define GSMEM (OFF_STG + 3 * STAGE_BYTES)   // 74752

__device__ __forceinline__ uint32_t swz(int row, int grp) {
    return (uint32_t)row * 64 + (uint32_t)((grp ^ ((row >> 1) & 3)) << 4);
}

__device__ __forceinline__ void fill_stage(
    uint32_t stg, const __half* __restrict__ aP, int k0A,
    const __half* __restrict__ wh, const __half* __restrict__ wl, int k0W,
    int row0, int tid) {
#pragma unroll
    for (int q = 0; q < 2; ++q) {
        const int i = tid * 2 + q;      // 0..511
        const int row = i >> 2;         // 0..127
        const int grp = i & 3;          // 16B group
        const uint32_t d = swz(row, grp);
        const int gr = row0 + row;
        if (gr < N_NODES) {
            cp16(stg + PL_A + d, aP + (size_t)gr * D + k0A + grp * 8);
        } else {
            asm volatile("st.shared.v4.b32 [%0], {%1,%1,%1,%1};"
                         :: "r"(stg + PL_A + d), "r"(0));
        }
        cp16(stg + PL_WH + d, wh + row * 256 + k0W + grp * 8);
        cp16(stg + PL_WL + d, wl + row * 256 + k0W + grp * 8);
    }
}

__global__ __launch_bounds__(256) void gemm_v3_kernel(
    const __half* __restrict__ hinP,
    const __half* __restrict__ WH,    // [128][256] this layer
    const __half* __restrict__ WL,
    const float* __restrict__ bias,
    float* __restrict__ out,          // may be null
    __half* __restrict__ outP,        // may be null
    int do_relu) {
    extern __shared__ char smem[];
    const uint32_t sb = smem_u32(smem);
    const int tid = threadIdx.x;
    const int wid = tid >> 5;
    const int lane = tid & 31;
    const int row0 = blockIdx.x * 128;
    const int wm = wid >> 2;
    const int wn = wid & 3;

    if (tid < 128) ((float*)smem)[tid] = bias[tid];

    float acc[4][4][4];
#pragma unroll
    for (int i = 0; i < 4; ++i)
#pragma unroll
        for (int j = 0; j < 4; ++j)
#pragma unroll
            for (int r = 0; r < 4; ++r) acc[i][j][r] = 0.f;

#pragma unroll
    for (int t = 0; t < 3; ++t) {
        const __half* aP = (t < 4) ? g_aggP : hinP;
        fill_stage(sb + OFF_STG + t * STAGE_BYTES, aP, (t & 3) * 32,
                   WH, WL, t * 32, row0, tid);
        asm volatile("cp.async.commit_group;" ::: "memory");
    }

    for (int t = 0; t < 8; ++t) {
        asm volatile("cp.async.wait_group 2;" ::: "memory");
        __syncthreads();

        const uint32_t stg = sb + OFF_STG + (t % 3) * STAGE_BYTES;
#pragma unroll
        for (int ks = 0; ks < 2; ++ks) {
            const int kb = ks * 16;
            uint32_t af[4][4];
#pragma unroll
            for (int i = 0; i < 4; ++i) {
                const int m0 = wm * 64 + i * 16;
                const int r = m0 + (lane & 7) + ((lane & 8) ? 8 : 0);
                const int g = (kb >> 3) + (lane >> 4);
                ldsm_x4(af[i], stg + PL_A + swz(r, g));
            }
            uint32_t bh[4][2], bl[4][2];
#pragma unroll
            for (int j = 0; j < 4; ++j) {
                const int n0 = wn * 32 + j * 8;
                const int l15 = lane & 15;
                const int r = n0 + (l15 & 7);
                const int g = (kb >> 3) + (l15 >> 3);
                ldsm_x2(bh[j], stg + PL_WH + swz(r, g));
                ldsm_x2(bl[j], stg + PL_WL + swz(r, g));
            }
#pragma unroll
            for (int i = 0; i < 4; ++i)
#pragma unroll
                for (int j = 0; j < 4; ++j) {
                    mma_f16(acc[i][j], af[i], bh[j]);
                    mma_f16(acc[i][j], af[i], bl[j]);
                }
        }
        __syncthreads();

        const int tn = t + 3;
        if (tn < 8) {
            const __half* aP = (tn < 4) ? g_aggP : hinP;
            fill_stage(sb + OFF_STG + (tn % 3) * STAGE_BYTES, aP, (tn & 3) * 32,
                       WH, WL, tn * 32, row0, tid);
        }
        asm volatile("cp.async.commit_group;" ::: "memory");
    }

    // epilogue
    const float* sB = (const float*)smem;
    const int lr = lane >> 2;
    const int lc = (lane & 3) * 2;
#pragma unroll
    for (int i = 0; i < 4; ++i) {
        const int rows[2] = { row0 + wm * 64 + i * 16 + lr,
                              row0 + wm * 64 + i * 16 + lr + 8 };
#pragma unroll
        for (int j = 0; j < 4; ++j) {
            const int col = wn * 32 + j * 8 + lc;
            const float bx = sB[col], by = sB[col + 1];
#pragma unroll
            for (int hh = 0; hh < 2; ++hh) {
                const int r = rows[hh];
                if (r < N_NODES) {
                    float2 o;
                    o.x = acc[i][j][hh * 2 + 0] + bx;
                    o.y = acc[i][j][hh * 2 + 1] + by;
                    if (do_relu) { o.x = fmaxf(o.x, 0.f); o.y = fmaxf(o.y, 0.f); }
                    if (out)
                        *reinterpret_cast<float2*>(out + (size_t)r * D + col) = o;
                    if (outP) {
                        __half2 hp = __floats2half2_rn(o.x, o.y);
                        *reinterpret_cast<uint32_t*>(
                            reinterpret_cast<char*>(outP) + ((size_t)r * D + col) * 2) =
                            *reinterpret_cast<uint32_t*>(&hp);
                    }
                }
            }
        }
    }
}

// ===========================================================================
// Launch
// ===========================================================================
extern "C" void kernel_launch(void* const* d_in, const int* in_sizes, int n_in,
                              void* d_out, int out_size) {
    const float* x   = (const float*)d_in[0];
    const float* ew  = (const float*)d_in[1];
    const float* Wr0 = (const float*)d_in[2];
    const float* Wo0 = (const float*)d_in[3];
    const float* b0  = (const float*)d_in[4];
    const float* Wr1 = (const float*)d_in[5];
    const float* Wo1 = (const float*)d_in[6];
    const float* b1  = (const float*)d_in[7];
    const float* Wr2 = (const float*)d_in[8];
    const float* Wo2 = (const float*)d_in[9];
    const float* b2  = (const float*)d_in[10];
    const int* src   = (const int*)d_in[11];
    const int* dst   = (const int*)d_in[12];
    float* out = (float*)d_out;

    __half *p0 = nullptr, *p1 = nullptr, *whB = nullptr, *wlB = nullptr;
    cudaGetSymbolAddress((void**)&p0, g_P0);
    cudaGetSymbolAddress((void**)&p1, g_P1);
    cudaGetSymbolAddress((void**)&whB, g_WH);
    cudaGetSymbolAddress((void**)&wlB, g_WL);

    cudaFuncSetAttribute(gemm_v3_kernel, cudaFuncAttributeMaxDynamicSharedMemorySize, GSMEM);

    const int edge_blocks = (N_EDGES + 255) / 256;
    const int agg_blocks  = (N_NODES * 32 + 255) / 256;
    const int gemm_blocks = (N_NODES + 127) / 128;

    // one-time preprocessing
    zero_deg_kernel<<<NB_SCAN, 256>>>();
    hist_kernel<<<edge_blocks, 256>>>(dst);
    presplit_w_kernel<<<384, 256>>>(Wr0, Wo0, Wr1, Wo1, Wr2, Wo2);
    split_x_kernel<<<25000, 256>>>(x);
    blocksum_kernel<<<NB_SCAN, 256>>>();
    scan_bsum_kernel<<<1, 512>>>();
    offsets_kernel<<<NB_SCAN, 256>>>();
    scatter_kernel<<<edge_blocks, 256>>>(src, dst, ew);

    // Layer 0: A = [agg(P0) | P0] -> plane P1
    agg_kernel<<<agg_blocks, 256>>>(p0);
    gemm_v3_kernel<<<gemm_blocks, 256, GSMEM>>>(p0, whB, wlB, b0, nullptr, p1, 1);

    // Layer 1: A = [agg(P1) | P1] -> plane P0
    agg_kernel<<<agg_blocks, 256>>>(p1);
    gemm_v3_kernel<<<gemm_blocks, 256, GSMEM>>>(p1, whB + 32768, wlB + 32768, b1, nullptr, p0, 1);

    // Layer 2: A = [agg(P0) | P0] -> fp32 out
    agg_kernel<<<agg_blocks, 256>>>(p0);
    gemm_v3_kernel<<<gemm_blocks, 256, GSMEM>>>(p0, whB + 65536, wlB + 65536, b2, out, nullptr, 0);
}